// round 12
// baseline (speedup 1.0000x reference)
#include <cuda_runtime.h>

// x:   [B=2, 1, D=64, H=256, W=256] fp32
// out: [B=2, 16, D=64, H=256, W=256] fp32
//   even channel -> per-slice 2D sobel magnitude, odd channel -> x
//
// R4 structure (empirical best). Single-variable A/B vs R4: write-through
// stores (__stwt) instead of evict-first (__stcs) — the one remaining
// untested L2 write path for the dominant 512MiB store stream.

#define W 256
#define H 256
#define DD 64
#define NB 2

__device__ __forceinline__ float fsqrt_approx(float a) {
    float r;
    asm("sqrt.approx.f32 %0, %1;" : "=f"(r) : "f"(a));
    return r;
}

__global__ __launch_bounds__(256) void sobel_cat_kernel(
    const float* __restrict__ x, float* __restrict__ out)
{
    const int warp = blockIdx.x * (blockDim.x >> 5) + (threadIdx.x >> 5);
    const int lane = threadIdx.x & 31;
    const int h    = warp & (H - 1);
    const int bd   = warp >> 8;          // b*D + d
    const int w0   = lane << 2;          // chunk0: px w0..w0+3, chunk1: +128

    const float* base = x + ((size_t)bd * H + h) * W + w0;
    const bool ht = (h > 0), hb = (h < H - 1);

    float4 z = make_float4(0.f, 0.f, 0.f, 0.f);
    float4 t0 = z, t1 = z, b0 = z, b1 = z;
    float4 m0 = __ldg((const float4*)base);
    float4 m1 = __ldg((const float4*)(base + 128));
    if (ht) { t0 = __ldg((const float4*)(base - W));
              t1 = __ldg((const float4*)(base + 128 - W)); }
    if (hb) { b0 = __ldg((const float4*)(base + W));
              b1 = __ldg((const float4*)(base + 128 + W)); }

    const unsigned full = 0xFFFFFFFFu;

    // chunk0 halos
    float t0l = __shfl_up_sync(full, t0.w, 1);
    float m0l = __shfl_up_sync(full, m0.w, 1);
    float b0l = __shfl_up_sync(full, b0.w, 1);
    float t0r = __shfl_down_sync(full, t0.x, 1);
    float m0r = __shfl_down_sync(full, m0.x, 1);
    float b0r = __shfl_down_sync(full, b0.x, 1);
    float t1x0 = __shfl_sync(full, t1.x, 0);
    float m1x0 = __shfl_sync(full, m1.x, 0);
    float b1x0 = __shfl_sync(full, b1.x, 0);
    if (lane == 0)  { t0l = 0.f; m0l = 0.f; b0l = 0.f; }
    if (lane == 31) { t0r = t1x0; m0r = m1x0; b0r = b1x0; }

    // chunk1 halos
    float t1l = __shfl_up_sync(full, t1.w, 1);
    float m1l = __shfl_up_sync(full, m1.w, 1);
    float b1l = __shfl_up_sync(full, b1.w, 1);
    float t1r = __shfl_down_sync(full, t1.x, 1);
    float m1r = __shfl_down_sync(full, m1.x, 1);
    float b1r = __shfl_down_sync(full, b1.x, 1);
    float t0w31 = __shfl_sync(full, t0.w, 31);
    float m0w31 = __shfl_sync(full, m0.w, 31);
    float b0w31 = __shfl_sync(full, b0.w, 31);
    if (lane == 0)  { t1l = t0w31; m1l = m0w31; b1l = b0w31; }
    if (lane == 31) { t1r = 0.f; m1r = 0.f; b1r = 0.f; }

    float4 s0, s1;
    {
        float T[6] = { t0l, t0.x, t0.y, t0.z, t0.w, t0r };
        float M[6] = { m0l, m0.x, m0.y, m0.z, m0.w, m0r };
        float Bt[6] = { b0l, b0.x, b0.y, b0.z, b0.w, b0r };
        float* s = reinterpret_cast<float*>(&s0);
#pragma unroll
        for (int i = 0; i < 4; i++) {
            float gx = (T[i+2] - T[i]) + 2.f*(M[i+2] - M[i]) + (Bt[i+2] - Bt[i]);
            float gy = (Bt[i] - T[i]) + 2.f*(Bt[i+1] - T[i+1]) + (Bt[i+2] - T[i+2]);
            s[i] = fsqrt_approx(gx*gx + gy*gy);
        }
    }
    {
        float T[6] = { t1l, t1.x, t1.y, t1.z, t1.w, t1r };
        float M[6] = { m1l, m1.x, m1.y, m1.z, m1.w, m1r };
        float Bt[6] = { b1l, b1.x, b1.y, b1.z, b1.w, b1r };
        float* s = reinterpret_cast<float*>(&s1);
#pragma unroll
        for (int i = 0; i < 4; i++) {
            float gx = (T[i+2] - T[i]) + 2.f*(M[i+2] - M[i]) + (Bt[i+2] - Bt[i]);
            float gy = (Bt[i] - T[i]) + 2.f*(Bt[i+1] - T[i+1]) + (Bt[i+2] - T[i+2]);
            s[i] = fsqrt_approx(gx*gx + gy*gy);
        }
    }

    const int b = bd >> 6;           // bd / D
    const int d = bd & (DD - 1);     // bd % D
    const size_t cs = (size_t)DD * H * W;  // channel stride (elems)
    float* obase = out + (((size_t)b * 16 * DD + d) * H + h) * W + w0;

#pragma unroll
    for (int c = 0; c < 8; c++) {
        float* p = obase + (size_t)(2 * c) * cs;   // sobel channel
        __stwt((float4*)p,           s0);
        __stwt((float4*)(p + 128),   s1);
        float* q = p + cs;                         // copy channel
        __stwt((float4*)q,           m0);
        __stwt((float4*)(q + 128),   m1);
    }
}

extern "C" void kernel_launch(void* const* d_in, const int* in_sizes, int n_in,
                              void* d_out, int out_size)
{
    const float* x = (const float*)d_in[0];
    float* out = (float*)d_out;

    // one warp per row: NB*DD*H = 32768 warps, 8 warps per block
    const int total_warps = NB * DD * H;
    const int threads = 256;
    const int blocks = total_warps * 32 / threads;   // 4096
    sobel_cat_kernel<<<blocks, threads>>>(x, out);
}

// round 13
// speedup vs baseline: 1.0506x; 1.0506x over previous
#include <cuda_runtime.h>

// x:   [B=2, 1, D=64, H=256, W=256] fp32
// out: [B=2, 16, D=64, H=256, W=256] fp32
//   even channel -> per-slice 2D sobel magnitude, odd channel -> x
//
// FINAL (R4 config; best of 12 rounds, reproduced 3x at ~84.5us wall).
// The kernel is HBM-write-ceiling bound: ~510MB compulsory store stream at
// ~5.9-6.0 TB/s effective (DRAM ~74-75%), no SM-side unit above 80%. Tested
// and null: load vectorization, 256b stores, TMA bulk 8KB bursts, .cs vs
// default vs .wt store policy, occupancy 20-87%, regs 32/39/57, 1/2/8-row
// tiles. Structure:
//   - one warp = one full 256-px row; lane owns chunks at w=4l and w=4l+128
//   - all halos via warp shuffle (zero scalar edge loads)
//   - sqrt.approx.f32 (single MUFU op; sobel computed exactly once/pixel)
//   - 32 fully-coalesced evict-first STG.128 per thread (16-channel fan-out)

#define W 256
#define H 256
#define DD 64
#define NB 2

__device__ __forceinline__ float fsqrt_approx(float a) {
    float r;
    asm("sqrt.approx.f32 %0, %1;" : "=f"(r) : "f"(a));
    return r;
}

__global__ __launch_bounds__(256) void sobel_cat_kernel(
    const float* __restrict__ x, float* __restrict__ out)
{
    const int warp = blockIdx.x * (blockDim.x >> 5) + (threadIdx.x >> 5);
    const int lane = threadIdx.x & 31;
    const int h    = warp & (H - 1);
    const int bd   = warp >> 8;          // b*D + d
    const int w0   = lane << 2;          // chunk0: px w0..w0+3, chunk1: +128

    const float* base = x + ((size_t)bd * H + h) * W + w0;
    const bool ht = (h > 0), hb = (h < H - 1);

    float4 z = make_float4(0.f, 0.f, 0.f, 0.f);
    float4 t0 = z, t1 = z, b0 = z, b1 = z;
    float4 m0 = __ldg((const float4*)base);
    float4 m1 = __ldg((const float4*)(base + 128));
    if (ht) { t0 = __ldg((const float4*)(base - W));
              t1 = __ldg((const float4*)(base + 128 - W)); }
    if (hb) { b0 = __ldg((const float4*)(base + W));
              b1 = __ldg((const float4*)(base + 128 + W)); }

    const unsigned full = 0xFFFFFFFFu;

    // chunk0 halos: left = lane-1 c0.w (lane0 -> 0 pad),
    //               right = lane+1 c0.x (lane31 -> c1.x of lane0)
    float t0l = __shfl_up_sync(full, t0.w, 1);
    float m0l = __shfl_up_sync(full, m0.w, 1);
    float b0l = __shfl_up_sync(full, b0.w, 1);
    float t0r = __shfl_down_sync(full, t0.x, 1);
    float m0r = __shfl_down_sync(full, m0.x, 1);
    float b0r = __shfl_down_sync(full, b0.x, 1);
    float t1x0 = __shfl_sync(full, t1.x, 0);
    float m1x0 = __shfl_sync(full, m1.x, 0);
    float b1x0 = __shfl_sync(full, b1.x, 0);
    if (lane == 0)  { t0l = 0.f; m0l = 0.f; b0l = 0.f; }
    if (lane == 31) { t0r = t1x0; m0r = m1x0; b0r = b1x0; }

    // chunk1 halos: left = lane-1 c1.w (lane0 -> c0.w of lane31),
    //               right = lane+1 c1.x (lane31 -> 0 pad)
    float t1l = __shfl_up_sync(full, t1.w, 1);
    float m1l = __shfl_up_sync(full, m1.w, 1);
    float b1l = __shfl_up_sync(full, b1.w, 1);
    float t1r = __shfl_down_sync(full, t1.x, 1);
    float m1r = __shfl_down_sync(full, m1.x, 1);
    float b1r = __shfl_down_sync(full, b1.x, 1);
    float t0w31 = __shfl_sync(full, t0.w, 31);
    float m0w31 = __shfl_sync(full, m0.w, 31);
    float b0w31 = __shfl_sync(full, b0.w, 31);
    if (lane == 0)  { t1l = t0w31; m1l = m0w31; b1l = b0w31; }
    if (lane == 31) { t1r = 0.f; m1r = 0.f; b1r = 0.f; }

    float4 s0, s1;
    {
        float T[6] = { t0l, t0.x, t0.y, t0.z, t0.w, t0r };
        float M[6] = { m0l, m0.x, m0.y, m0.z, m0.w, m0r };
        float Bt[6] = { b0l, b0.x, b0.y, b0.z, b0.w, b0r };
        float* s = reinterpret_cast<float*>(&s0);
#pragma unroll
        for (int i = 0; i < 4; i++) {
            float gx = (T[i+2] - T[i]) + 2.f*(M[i+2] - M[i]) + (Bt[i+2] - Bt[i]);
            float gy = (Bt[i] - T[i]) + 2.f*(Bt[i+1] - T[i+1]) + (Bt[i+2] - T[i+2]);
            s[i] = fsqrt_approx(gx*gx + gy*gy);
        }
    }
    {
        float T[6] = { t1l, t1.x, t1.y, t1.z, t1.w, t1r };
        float M[6] = { m1l, m1.x, m1.y, m1.z, m1.w, m1r };
        float Bt[6] = { b1l, b1.x, b1.y, b1.z, b1.w, b1r };
        float* s = reinterpret_cast<float*>(&s1);
#pragma unroll
        for (int i = 0; i < 4; i++) {
            float gx = (T[i+2] - T[i]) + 2.f*(M[i+2] - M[i]) + (Bt[i+2] - Bt[i]);
            float gy = (Bt[i] - T[i]) + 2.f*(Bt[i+1] - T[i+1]) + (Bt[i+2] - T[i+2]);
            s[i] = fsqrt_approx(gx*gx + gy*gy);
        }
    }

    const int b = bd >> 6;           // bd / D
    const int d = bd & (DD - 1);     // bd % D
    const size_t cs = (size_t)DD * H * W;  // channel stride (elems)
    float* obase = out + (((size_t)b * 16 * DD + d) * H + h) * W + w0;

#pragma unroll
    for (int c = 0; c < 8; c++) {
        float* p = obase + (size_t)(2 * c) * cs;   // sobel channel
        __stcs((float4*)p,           s0);
        __stcs((float4*)(p + 128),   s1);
        float* q = p + cs;                         // copy channel
        __stcs((float4*)q,           m0);
        __stcs((float4*)(q + 128),   m1);
    }
}

extern "C" void kernel_launch(void* const* d_in, const int* in_sizes, int n_in,
                              void* d_out, int out_size)
{
    const float* x = (const float*)d_in[0];
    float* out = (float*)d_out;

    // one warp per row: NB*DD*H = 32768 warps, 8 warps per block
    const int total_warps = NB * DD * H;
    const int threads = 256;
    const int blocks = total_warps * 32 / threads;   // 4096
    sobel_cat_kernel<<<blocks, threads>>>(x, out);
}